// round 10
// baseline (speedup 1.0000x reference)
#include <cuda_runtime.h>
#include <cuda_fp16.h>
#include <math.h>
#include <stdint.h>

// ---------------- problem constants ----------------
#define SN_     32
#define NROI    512
#define NCH     480
#define TFRM    4
#define FY      45
#define FX      80
#define OSZ     7
#define DIN     23520
#define NDF     1024
#define NCLUS   50
#define KTOT    23520
#define KPAD    23552          // 736 k-tiles of 32
#define SPLITK  23
#define KT_PER  32             // 736 / 23

// GEMM tiling
#define BM 128
#define BN 128
#define BK 32                  // fp16 elems per k-tile (64B rows)
#define SROW 80                // 64B data + 16B pad (conflict-free ldsm)
#define SUBT_B (BM * SROW)     // 10240 per sub-tile
#define ASTAGE_B (2 * SUBT_B)  // Ah + Al = 20480
#define NSTAGE_A 5
#define BSTAGE_B (2 * SUBT_B)  // Bh + Bl = 20480
#define SMEM_A_TOT (NSTAGE_A * ASTAGE_B)          // 102400
#define SMEM_DYN (SMEM_A_TOT + 2 * BSTAGE_B)      // 143360

// ---------------- scratch ----------------
__device__ __align__(128) __half g_pl_hi[(size_t)NROI * KPAD];   // 24 MB
__device__ __align__(128) __half g_pl_lo[(size_t)NROI * KPAD];   // 24 MB
__device__ float g_partial[(size_t)SPLITK * NROI * NDF];         // 48 MB

// ---------------- helpers ----------------
__device__ __forceinline__ uint32_t smem_u32(const void* p) {
    uint32_t a;
    asm("{ .reg .u64 t; cvta.to.shared.u64 t, %1; cvt.u32.u64 %0, t; }" : "=r"(a) : "l"(p));
    return a;
}
__device__ __forceinline__ void cp_async16(uint32_t dst, const void* src) {
    asm volatile("cp.async.cg.shared.global [%0], [%1], 16;" :: "r"(dst), "l"(src) : "memory");
}
__device__ __forceinline__ void cp_commit() {
    asm volatile("cp.async.commit_group;" ::: "memory");
}
template <int N>
__device__ __forceinline__ void cp_wait() {
    asm volatile("cp.async.wait_group %0;" :: "n"(N) : "memory");
}
__device__ __forceinline__ void ldsm_x4(uint32_t* r, uint32_t addr) {
    asm volatile("ldmatrix.sync.aligned.m8n8.x4.shared.b16 {%0,%1,%2,%3}, [%4];"
                 : "=r"(r[0]), "=r"(r[1]), "=r"(r[2]), "=r"(r[3]) : "r"(addr));
}
__device__ __forceinline__ void mma_f16(float* c, const uint32_t* a, uint32_t b0, uint32_t b1) {
    asm volatile(
        "mma.sync.aligned.m16n8k16.row.col.f32.f16.f16.f32 "
        "{%0,%1,%2,%3}, {%4,%5,%6,%7}, {%8,%9}, {%0,%1,%2,%3};"
        : "+f"(c[0]), "+f"(c[1]), "+f"(c[2]), "+f"(c[3])
        : "r"(a[0]), "r"(a[1]), "r"(a[2]), "r"(a[3]), "r"(b0), "r"(b1));
}
__device__ __forceinline__ float nan_to_num(float v) {
    if (isnan(v)) return 0.0f;
    if (isinf(v)) return v > 0.0f ? 3.4028234663852886e38f : -3.4028234663852886e38f;
    return v;
}
// split two floats -> packed fp16 hi pair + lo pair
__device__ __forceinline__ void split2(float x, float y, uint32_t& hi, uint32_t& lo) {
    __half2 h = __floats2half2_rn(x, y);
    float2 hf = __half22float2(h);
    __half2 l = __floats2half2_rn(x - hf.x, y - hf.y);
    hi = *(uint32_t*)&h;
    lo = *(uint32_t*)&l;
}

// ---------------- kernel 1: RoI align -> fp16 hi/lo pooled (round-8 mapping) ----------------
__global__ void roi_pool_kernel(const float* __restrict__ zvis,
                                const float* __restrict__ bboxs) {
    __shared__ int   s_off[49][4];
    __shared__ float s_w[49][4];

    const int r   = blockIdx.x;
    const int b   = r / SN_;
    const int tid = threadIdx.x;

    if (tid < 49) {
        const float* bb = bboxs + (size_t)r * 4;
        const float sc = 0.0625f;
        float x1 = nan_to_num(bb[0] * sc) - 0.5f;
        float y1 = nan_to_num(bb[1] * sc) - 0.5f;
        float x2 = nan_to_num(bb[2] * sc) - 0.5f;
        float y2 = nan_to_num(bb[3] * sc) - 0.5f;
        float bw = (x2 - x1) * (1.0f / OSZ);
        float bh = (y2 - y1) * (1.0f / OSZ);

        int py = tid / OSZ, px = tid - py * OSZ;
        float y = y1 + ((float)py + 0.5f) * bh;
        float x = x1 + ((float)px + 0.5f) * bw;
        bool valid = (y > -1.0f) && (y < (float)FY) && (x > -1.0f) && (x < (float)FX);
        float yc = fminf(fmaxf(y, 0.0f), (float)(FY - 1));
        float xc = fminf(fmaxf(x, 0.0f), (float)(FX - 1));
        int yl = (int)floorf(yc);
        int xl = (int)floorf(xc);
        int yh = min(yl + 1, FY - 1);
        int xh = min(xl + 1, FX - 1);
        float ly = yc - (float)yl, lx = xc - (float)xl;
        float hy = 1.0f - ly, hx = 1.0f - lx;
        float vm = valid ? 1.0f : 0.0f;

        s_off[tid][0] = yl * FX + xl;
        s_off[tid][1] = yl * FX + xh;
        s_off[tid][2] = yh * FX + xl;
        s_off[tid][3] = yh * FX + xh;
        s_w[tid][0] = hy * hx * vm;
        s_w[tid][1] = hy * lx * vm;
        s_w[tid][2] = ly * hx * vm;
        s_w[tid][3] = ly * lx * vm;
    }
    __syncthreads();

    const float* fbase = zvis + (size_t)b * NCH * TFRM * FY * FX + (size_t)3 * FY * FX;
    __half* ohi = g_pl_hi + (size_t)r * KPAD;
    __half* olo = g_pl_lo + (size_t)r * KPAD;

    for (int k = tid; k < DIN; k += 256) {
        int c = k / 49;
        int p = k - c * 49;
        const float* f = fbase + (size_t)c * (TFRM * FY * FX);
        float v = s_w[p][0] * f[s_off[p][0]]
                + s_w[p][1] * f[s_off[p][1]]
                + s_w[p][2] * f[s_off[p][2]]
                + s_w[p][3] * f[s_off[p][3]];
        __half h = __float2half_rn(v);
        ohi[k] = h;
        olo[k] = __float2half_rn(v - __half2float(h));
    }
    if (tid < (KPAD - DIN)) {
        ohi[DIN + tid] = __float2half_rn(0.0f);
        olo[DIN + tid] = __float2half_rn(0.0f);
    }
}

// ---------------- kernel 2: fp16 three-term HMMA GEMM ----------------
// acc = Ah*Bh + Al*Bh + Ah*Bl.  A: cp.async fp16 hi/lo (5 stages).
// B: f32 LDG from w_vis 2 tiles ahead -> in-register split -> STS (2 buffers).
__global__ void __launch_bounds__(256) gemm_hmma(const float* __restrict__ Wv) {
    extern __shared__ __align__(16) char smem[];

    const int tid   = threadIdx.x;
    const int warp  = tid >> 5;
    const int lane  = tid & 31;
    const int nBase = blockIdx.x * BN;
    const int mBase = blockIdx.y * BM;
    const int z     = blockIdx.z;

    const uint32_t sbase = smem_u32(smem);
    const uint32_t sbB   = sbase + SMEM_A_TOT;

    // A loader mapping
    const int lrow = tid >> 2;        // 0..63
    const int lseg = tid & 3;         // 16B segment

    // B loader mapping: 2 threads per row, 64B (16 floats) each
    const int brow_ld = tid >> 1;     // 0..127
    const int bhalf   = tid & 1;      // 0..1

    // compute mapping
    const int warpM = warp >> 2;      // 0..1 -> *64
    const int warpN = warp & 3;       // 0..3 -> *32
    const uint32_t a_row = (uint32_t)(warpM * 64 + (lane & 15));
    const uint32_t a_seg = (uint32_t)(lane >> 4);
    const uint32_t b_row = (uint32_t)(warpN * 32 + ((lane >> 4) << 3) + (lane & 7));
    const uint32_t b_seg = (uint32_t)((lane >> 3) & 1);

    float acc[4][4][4];
    #pragma unroll
    for (int i = 0; i < 4; ++i)
        #pragma unroll
        for (int j = 0; j < 4; ++j)
            #pragma unroll
            for (int q = 0; q < 4; ++q) acc[i][j][q] = 0.0f;

    float4 breg[2][4];

    auto ldg_B = [&](int buf, int kt) {
        const int koff = (z * KT_PER + kt) * BK;
        if (koff < KTOT) {
            const float* p = Wv + (size_t)(nBase + brow_ld) * KTOT + koff + bhalf * 16;
            #pragma unroll
            for (int s = 0; s < 4; ++s) breg[buf][s] = *(const float4*)(p + s * 4);
        } else {
            #pragma unroll
            for (int s = 0; s < 4; ++s) breg[buf][s] = make_float4(0.f, 0.f, 0.f, 0.f);
        }
    };

    auto sts_B = [&](int buf, int bs) {
        uint4 h0, l0, h1, l1;
        split2(breg[buf][0].x, breg[buf][0].y, h0.x, l0.x);
        split2(breg[buf][0].z, breg[buf][0].w, h0.y, l0.y);
        split2(breg[buf][1].x, breg[buf][1].y, h0.z, l0.z);
        split2(breg[buf][1].z, breg[buf][1].w, h0.w, l0.w);
        split2(breg[buf][2].x, breg[buf][2].y, h1.x, l1.x);
        split2(breg[buf][2].z, breg[buf][2].w, h1.y, l1.y);
        split2(breg[buf][3].x, breg[buf][3].y, h1.z, l1.z);
        split2(breg[buf][3].z, breg[buf][3].w, h1.w, l1.w);
        char* base = smem + SMEM_A_TOT + bs * BSTAGE_B + brow_ld * SROW + bhalf * 32;
        *(uint4*)(base)              = h0;
        *(uint4*)(base + 16)         = h1;
        *(uint4*)(base + SUBT_B)     = l0;
        *(uint4*)(base + SUBT_B + 16) = l1;
    };

    auto load_stageA = [&](int s, int kt) {
        const int koff = (z * KT_PER + kt) * BK;
        const uint32_t st = sbase + s * ASTAGE_B;
        const __half* ah0 = g_pl_hi + (size_t)(mBase + lrow)      * KPAD + koff + lseg * 8;
        const __half* ah1 = g_pl_hi + (size_t)(mBase + lrow + 64) * KPAD + koff + lseg * 8;
        const __half* al0 = g_pl_lo + (size_t)(mBase + lrow)      * KPAD + koff + lseg * 8;
        const __half* al1 = g_pl_lo + (size_t)(mBase + lrow + 64) * KPAD + koff + lseg * 8;
        cp_async16(st +          lrow * SROW        + lseg * 16, ah0);
        cp_async16(st +         (lrow + 64) * SROW  + lseg * 16, ah1);
        cp_async16(st + SUBT_B + lrow * SROW        + lseg * 16, al0);
        cp_async16(st + SUBT_B + (lrow + 64) * SROW + lseg * 16, al1);
        cp_commit();
    };

    // prologue
    load_stageA(0, 0);
    load_stageA(1, 1);
    load_stageA(2, 2);
    load_stageA(3, 3);
    ldg_B(0, 0);
    sts_B(0, 0);            // B buffer 0 <- kt 0 (visible after first barrier)
    ldg_B(1, 1);

    for (int kt = 0; kt < KT_PER; ++kt) {
        cp_wait<3>();
        __syncthreads();

        // stage B for kt+1 (readers of this buffer finished before the barrier above)
        if (kt + 1 < KT_PER) sts_B((kt + 1) & 1, (kt + 1) & 1);
        if (kt + 2 < KT_PER) ldg_B(kt & 1, kt + 2);
        if (kt + 4 < KT_PER) load_stageA((kt + 4) % NSTAGE_A, kt + 4);

        const uint32_t st  = sbase + (kt % NSTAGE_A) * ASTAGE_B;
        const uint32_t sah = st;
        const uint32_t sal = st + SUBT_B;
        const uint32_t sbh = sbB + (kt & 1) * BSTAGE_B;
        const uint32_t sbl = sbh + SUBT_B;

        #pragma unroll
        for (int ks = 0; ks < 2; ++ks) {
            uint32_t bh[2][4], bl[2][4];
            #pragma unroll
            for (int pr = 0; pr < 2; ++pr) {
                ldsm_x4(bh[pr], sbh + (b_row + pr * 16) * SROW + (ks * 2 + b_seg) * 16);
                ldsm_x4(bl[pr], sbl + (b_row + pr * 16) * SROW + (ks * 2 + b_seg) * 16);
            }

            uint32_t ah[4][4], al[4][4];
            #pragma unroll
            for (int mf = 0; mf < 4; ++mf) {
                ldsm_x4(ah[mf], sah + (a_row + mf * 16) * SROW + (ks * 2 + a_seg) * 16);
                ldsm_x4(al[mf], sal + (a_row + mf * 16) * SROW + (ks * 2 + a_seg) * 16);
            }

            #pragma unroll
            for (int mf = 0; mf < 4; ++mf)
                #pragma unroll
                for (int nf = 0; nf < 4; ++nf)
                    mma_f16(acc[mf][nf], ah[mf], bh[nf >> 1][(nf & 1) * 2], bh[nf >> 1][(nf & 1) * 2 + 1]);
            #pragma unroll
            for (int mf = 0; mf < 4; ++mf)
                #pragma unroll
                for (int nf = 0; nf < 4; ++nf)
                    mma_f16(acc[mf][nf], al[mf], bh[nf >> 1][(nf & 1) * 2], bh[nf >> 1][(nf & 1) * 2 + 1]);
            #pragma unroll
            for (int mf = 0; mf < 4; ++mf)
                #pragma unroll
                for (int nf = 0; nf < 4; ++nf)
                    mma_f16(acc[mf][nf], ah[mf], bl[nf >> 1][(nf & 1) * 2], bl[nf >> 1][(nf & 1) * 2 + 1]);
        }
    }

    // epilogue -> g_partial[z][m][n]
    const int group = lane >> 2;
    const int quad  = lane & 3;
    #pragma unroll
    for (int mf = 0; mf < 4; ++mf) {
        int row0 = mBase + warpM * 64 + mf * 16 + group;
        #pragma unroll
        for (int nf = 0; nf < 4; ++nf) {
            int col = nBase + warpN * 32 + nf * 8 + quad * 2;
            float* p0 = g_partial + ((size_t)z * NROI + row0) * NDF + col;
            float* p1 = p0 + (size_t)8 * NDF;
            *(float2*)p0 = make_float2(acc[mf][nf][0], acc[mf][nf][1]);
            *(float2*)p1 = make_float2(acc[mf][nf][2], acc[mf][nf][3]);
        }
    }
}

// ---------------- kernel 3: fused reduce + bias + cluster (4 rois/block) ----------------
__global__ void cluster_fused_kernel(const float* __restrict__ norms,
                                     const float* __restrict__ b_vis,
                                     const float* __restrict__ w_spc,
                                     const float* __restrict__ b_spc,
                                     const float* __restrict__ cent,
                                     float* __restrict__ Z,
                                     float* __restrict__ out_s,
                                     float* __restrict__ out_c) {
    __shared__ __align__(16) float zrow[4][NDF];
    __shared__ float sdist[4][NCLUS];
    __shared__ float ssum[4];
    __shared__ int   sarg[4];

    const int m0  = blockIdx.x * 4;
    const int tid = threadIdx.x;
    float nm[4];
    #pragma unroll
    for (int j = 0; j < 4; ++j) nm[j] = norms[m0 + j];

    for (int d = tid; d < NDF; d += 256) {
        float base = b_vis[d] + b_spc[d];
        float w = w_spc[d];
        float a[4];
        #pragma unroll
        for (int j = 0; j < 4; ++j) a[j] = base + nm[j] * w;
        for (int zz = 0; zz < SPLITK; ++zz) {
            const float* pp = g_partial + ((size_t)zz * NROI + m0) * NDF + d;
            #pragma unroll
            for (int j = 0; j < 4; ++j) a[j] += pp[(size_t)j * NDF];
        }
        #pragma unroll
        for (int j = 0; j < 4; ++j) {
            zrow[j][d] = a[j];
            Z[(size_t)(m0 + j) * NDF + d] = a[j];
        }
    }
    __syncthreads();

    const int warp = tid >> 5;
    const int lane = tid & 31;
    for (int k = warp; k < NCLUS; k += 8) {
        const float4* ck = (const float4*)(cent + (size_t)k * NDF);
        float s[4] = {0.f, 0.f, 0.f, 0.f};
        #pragma unroll
        for (int i = 0; i < 8; ++i) {
            int d4 = i * 32 + lane;
            float4 c = ck[d4];
            #pragma unroll
            for (int j = 0; j < 4; ++j) {
                float4 zv = *(const float4*)&zrow[j][d4 * 4];
                float t;
                t = zv.x - c.x; s[j] += t * t;
                t = zv.y - c.y; s[j] += t * t;
                t = zv.z - c.z; s[j] += t * t;
                t = zv.w - c.w; s[j] += t * t;
            }
        }
        #pragma unroll
        for (int o = 16; o; o >>= 1)
            #pragma unroll
            for (int j = 0; j < 4; ++j)
                s[j] += __shfl_xor_sync(0xffffffffu, s[j], o);
        if (lane == 0)
            #pragma unroll
            for (int j = 0; j < 4; ++j) sdist[j][k] = sqrtf(s[j]);
    }
    __syncthreads();

    if (tid < 4) {
        float sum = 0.0f, best = -1.0f;
        int bi = 0;
        for (int k = 0; k < NCLUS; ++k) {
            float st = 1.0f / (1.0f + sdist[tid][k]);
            sum += st;
            if (st > best) { best = st; bi = k; }
        }
        ssum[tid] = sum;
        sarg[tid] = bi;
    }
    __syncthreads();

    {
        const int j = tid >> 6;          // 0..3
        const int kk = tid & 63;         // 0..63
        if (kk < NCLUS)
            out_s[(size_t)(m0 + j) * NCLUS + kk] = (1.0f / (1.0f + sdist[j][kk])) / ssum[j];
    }
    if (tid < 4) out_c[m0 + tid] = (float)sarg[tid];
}

// ---------------- launch ----------------
extern "C" void kernel_launch(void* const* d_in, const int* in_sizes, int n_in,
                              void* d_out, int out_size) {
    const float* z_vis     = (const float*)d_in[0];
    const float* bboxs     = (const float*)d_in[1];
    const float* norms     = (const float*)d_in[2];
    const float* w_vis     = (const float*)d_in[3];
    const float* b_vis     = (const float*)d_in[4];
    const float* w_spc     = (const float*)d_in[5];
    const float* b_spc     = (const float*)d_in[6];
    const float* centroids = (const float*)d_in[7];

    float* out = (float*)d_out;
    float* Z = out;
    float* S = out + (size_t)NROI * NDF;
    float* C = S + (size_t)NROI * NCLUS;

    cudaFuncSetAttribute(gemm_hmma, cudaFuncAttributeMaxDynamicSharedMemorySize, SMEM_DYN);

    roi_pool_kernel<<<NROI, 256>>>(z_vis, bboxs);

    dim3 gg(NDF / BN, NROI / BM, SPLITK);        // (8, 4, 23) = 736 CTAs
    gemm_hmma<<<gg, 256, SMEM_DYN>>>(w_vis);

    cluster_fused_kernel<<<NROI / 4, 256>>>(norms, b_vis, w_spc, b_spc, centroids, Z, S, C);
}

// round 11
// speedup vs baseline: 1.3968x; 1.3968x over previous
#include <cuda_runtime.h>
#include <cuda_fp16.h>
#include <math.h>
#include <stdint.h>

// ---------------- problem constants ----------------
#define SN_     32
#define NROI    512
#define NCH     480
#define TFRM    4
#define FY      45
#define FX      80
#define OSZ     7
#define DIN     23520
#define NDF     1024
#define NCLUS   50
#define KTOT    23520
#define KPAD    23552          // 736 k-tiles of 32
#define SPLITK  23
#define KT_PER  32             // 736 / 23

// roi split
#define ROIQ    4
#define ROICH   (DIN / ROIQ)   // 5880

// GEMM tiling
#define BM 128
#define BN 128
#define BK 32                  // fp16 elems per k-tile (64B rows)
#define SROW 80                // 64B data + 16B pad (conflict-free ldsm)
#define SUBT_B (BM * SROW)     // 10240 per sub-tile
#define STAGE_B (4 * SUBT_B)   // Ah + Al + Bh + Bl = 40960
#define NSTAGE 5
#define SMEM_DYN (NSTAGE * STAGE_B)   // 204800

// ---------------- scratch ----------------
__device__ __align__(128) __half g_pl_hi[(size_t)NROI * KPAD];   // 24 MB
__device__ __align__(128) __half g_pl_lo[(size_t)NROI * KPAD];   // 24 MB
__device__ __align__(128) __half g_w_hi [(size_t)NDF  * KPAD];   // 48 MB
__device__ __align__(128) __half g_w_lo [(size_t)NDF  * KPAD];   // 48 MB
__device__ float g_partial[(size_t)SPLITK * NROI * NDF];         // 48 MB

// ---------------- helpers ----------------
__device__ __forceinline__ uint32_t smem_u32(const void* p) {
    uint32_t a;
    asm("{ .reg .u64 t; cvta.to.shared.u64 t, %1; cvt.u32.u64 %0, t; }" : "=r"(a) : "l"(p));
    return a;
}
__device__ __forceinline__ void cp_async16(uint32_t dst, const void* src) {
    asm volatile("cp.async.cg.shared.global [%0], [%1], 16;" :: "r"(dst), "l"(src) : "memory");
}
__device__ __forceinline__ void cp_commit() {
    asm volatile("cp.async.commit_group;" ::: "memory");
}
template <int N>
__device__ __forceinline__ void cp_wait() {
    asm volatile("cp.async.wait_group %0;" :: "n"(N) : "memory");
}
__device__ __forceinline__ void ldsm_x4(uint32_t* r, uint32_t addr) {
    asm volatile("ldmatrix.sync.aligned.m8n8.x4.shared.b16 {%0,%1,%2,%3}, [%4];"
                 : "=r"(r[0]), "=r"(r[1]), "=r"(r[2]), "=r"(r[3]) : "r"(addr));
}
__device__ __forceinline__ void mma_f16(float* c, const uint32_t* a, uint32_t b0, uint32_t b1) {
    asm volatile(
        "mma.sync.aligned.m16n8k16.row.col.f32.f16.f16.f32 "
        "{%0,%1,%2,%3}, {%4,%5,%6,%7}, {%8,%9}, {%0,%1,%2,%3};"
        : "+f"(c[0]), "+f"(c[1]), "+f"(c[2]), "+f"(c[3])
        : "r"(a[0]), "r"(a[1]), "r"(a[2]), "r"(a[3]), "r"(b0), "r"(b1));
}
__device__ __forceinline__ float nan_to_num(float v) {
    if (isnan(v)) return 0.0f;
    if (isinf(v)) return v > 0.0f ? 3.4028234663852886e38f : -3.4028234663852886e38f;
    return v;
}
// split two floats -> packed fp16 hi pair + lo pair
__device__ __forceinline__ void split2(float x, float y, uint32_t& hi, uint32_t& lo) {
    __half2 h = __floats2half2_rn(x, y);
    float2 hf = __half22float2(h);
    __half2 l = __floats2half2_rn(x - hf.x, y - hf.y);
    hi = *(uint32_t*)&h;
    lo = *(uint32_t*)&l;
}

// ---------------- kernel 1: fused producers ----------------
// blocks [0, NROI*ROIQ): quarter-RoI-align -> pooled hi/lo fp16
// blocks [NROI*ROIQ, NROI*ROIQ+NDF): w_vis row -> w hi/lo fp16
__global__ void producers_kernel(const float* __restrict__ zvis,
                                 const float* __restrict__ bboxs,
                                 const float* __restrict__ Wv) {
    const int bid = blockIdx.x;
    const int tid = threadIdx.x;

    if (bid >= NROI * ROIQ) {
        // ---- w_vis conversion: 8 floats -> uint4 hi + uint4 lo per iter ----
        const int row = bid - NROI * ROIQ;
        const float4* s4 = (const float4*)(Wv + (size_t)row * KTOT);
        uint4* dh = (uint4*)(g_w_hi + (size_t)row * KPAD);
        uint4* dl = (uint4*)(g_w_lo + (size_t)row * KPAD);
        for (int c8 = tid; c8 < KPAD / 8; c8 += 256) {
            uint4 hi, lo;
            if (c8 < KTOT / 8) {
                float4 v0 = s4[c8 * 2];
                float4 v1 = s4[c8 * 2 + 1];
                split2(v0.x, v0.y, hi.x, lo.x);
                split2(v0.z, v0.w, hi.y, lo.y);
                split2(v1.x, v1.y, hi.z, lo.z);
                split2(v1.z, v1.w, hi.w, lo.w);
            } else {
                hi = make_uint4(0, 0, 0, 0);
                lo = make_uint4(0, 0, 0, 0);
            }
            dh[c8] = hi;
            dl[c8] = lo;
        }
        return;
    }

    // ---- quarter-RoI-align path ----
    __shared__ int   s_off[49][4];
    __shared__ float s_w[49][4];

    const int r = bid >> 2;           // roi index
    const int q = bid & 3;            // quarter index
    const int b = r / SN_;

    if (tid < 49) {
        const float* bb = bboxs + (size_t)r * 4;
        const float sc = 0.0625f;
        float x1 = nan_to_num(bb[0] * sc) - 0.5f;
        float y1 = nan_to_num(bb[1] * sc) - 0.5f;
        float x2 = nan_to_num(bb[2] * sc) - 0.5f;
        float y2 = nan_to_num(bb[3] * sc) - 0.5f;
        float bw = (x2 - x1) * (1.0f / OSZ);
        float bh = (y2 - y1) * (1.0f / OSZ);

        int py = tid / OSZ, px = tid - py * OSZ;
        float y = y1 + ((float)py + 0.5f) * bh;
        float x = x1 + ((float)px + 0.5f) * bw;
        bool valid = (y > -1.0f) && (y < (float)FY) && (x > -1.0f) && (x < (float)FX);
        float yc = fminf(fmaxf(y, 0.0f), (float)(FY - 1));
        float xc = fminf(fmaxf(x, 0.0f), (float)(FX - 1));
        int yl = (int)floorf(yc);
        int xl = (int)floorf(xc);
        int yh = min(yl + 1, FY - 1);
        int xh = min(xl + 1, FX - 1);
        float ly = yc - (float)yl, lx = xc - (float)xl;
        float hy = 1.0f - ly, hx = 1.0f - lx;
        float vm = valid ? 1.0f : 0.0f;

        s_off[tid][0] = yl * FX + xl;
        s_off[tid][1] = yl * FX + xh;
        s_off[tid][2] = yh * FX + xl;
        s_off[tid][3] = yh * FX + xh;
        s_w[tid][0] = hy * hx * vm;
        s_w[tid][1] = hy * lx * vm;
        s_w[tid][2] = ly * hx * vm;
        s_w[tid][3] = ly * lx * vm;
    }
    __syncthreads();

    const float* fbase = zvis + (size_t)b * NCH * TFRM * FY * FX + (size_t)3 * FY * FX;
    __half* ohi = g_pl_hi + (size_t)r * KPAD;
    __half* olo = g_pl_lo + (size_t)r * KPAD;

    const int kend = (q + 1) * ROICH;
    for (int k = q * ROICH + tid; k < kend; k += 256) {
        int c = k / 49;
        int p = k - c * 49;
        const float* f = fbase + (size_t)c * (TFRM * FY * FX);
        float v = s_w[p][0] * f[s_off[p][0]]
                + s_w[p][1] * f[s_off[p][1]]
                + s_w[p][2] * f[s_off[p][2]]
                + s_w[p][3] * f[s_off[p][3]];
        __half h = __float2half_rn(v);
        ohi[k] = h;
        olo[k] = __float2half_rn(v - __half2float(h));
    }
    if (q == 3 && tid < (KPAD - DIN)) {
        ohi[DIN + tid] = __float2half_rn(0.0f);
        olo[DIN + tid] = __float2half_rn(0.0f);
    }
}

// ---------------- kernel 2: fp16 three-term HMMA GEMM (split-K 23, 5-stage) ----------------
// acc = Ah*Bh + Al*Bh + Ah*Bl   (drops only Al*Bl ~ 2^-24)
__global__ void __launch_bounds__(256) gemm_hmma(int) {
    extern __shared__ __align__(16) char smem[];

    const int tid   = threadIdx.x;
    const int warp  = tid >> 5;
    const int lane  = tid & 31;
    const int nBase = blockIdx.x * BN;
    const int mBase = blockIdx.y * BM;
    const int z     = blockIdx.z;

    const uint32_t sbase = smem_u32(smem);

    // loader mapping
    const int lrow = tid >> 2;        // 0..63
    const int lseg = tid & 3;         // 16B segment

    // compute mapping
    const int warpM = warp >> 2;      // 0..1 -> *64
    const int warpN = warp & 3;       // 0..3 -> *32
    const uint32_t a_row = (uint32_t)(warpM * 64 + (lane & 15));
    const uint32_t a_seg = (uint32_t)(lane >> 4);
    const uint32_t b_row = (uint32_t)(warpN * 32 + ((lane >> 4) << 3) + (lane & 7));
    const uint32_t b_seg = (uint32_t)((lane >> 3) & 1);

    float acc[4][4][4];
    #pragma unroll
    for (int i = 0; i < 4; ++i)
        #pragma unroll
        for (int j = 0; j < 4; ++j)
            #pragma unroll
            for (int q = 0; q < 4; ++q) acc[i][j][q] = 0.0f;

    auto load_stage = [&](int s, int kt) {
        const int koff = (z * KT_PER + kt) * BK;
        const uint32_t st = sbase + s * STAGE_B;
        const __half* ah0 = g_pl_hi + (size_t)(mBase + lrow)      * KPAD + koff + lseg * 8;
        const __half* ah1 = g_pl_hi + (size_t)(mBase + lrow + 64) * KPAD + koff + lseg * 8;
        const __half* al0 = g_pl_lo + (size_t)(mBase + lrow)      * KPAD + koff + lseg * 8;
        const __half* al1 = g_pl_lo + (size_t)(mBase + lrow + 64) * KPAD + koff + lseg * 8;
        const __half* bh0 = g_w_hi + (size_t)(nBase + lrow)      * KPAD + koff + lseg * 8;
        const __half* bh1 = g_w_hi + (size_t)(nBase + lrow + 64) * KPAD + koff + lseg * 8;
        const __half* bl0 = g_w_lo + (size_t)(nBase + lrow)      * KPAD + koff + lseg * 8;
        const __half* bl1 = g_w_lo + (size_t)(nBase + lrow + 64) * KPAD + koff + lseg * 8;
        cp_async16(st +              lrow * SROW        + lseg * 16, ah0);
        cp_async16(st +             (lrow + 64) * SROW  + lseg * 16, ah1);
        cp_async16(st + SUBT_B     + lrow * SROW        + lseg * 16, al0);
        cp_async16(st + SUBT_B     + (lrow + 64) * SROW + lseg * 16, al1);
        cp_async16(st + 2 * SUBT_B + lrow * SROW        + lseg * 16, bh0);
        cp_async16(st + 2 * SUBT_B + (lrow + 64) * SROW + lseg * 16, bh1);
        cp_async16(st + 3 * SUBT_B + lrow * SROW        + lseg * 16, bl0);
        cp_async16(st + 3 * SUBT_B + (lrow + 64) * SROW + lseg * 16, bl1);
        cp_commit();
    };

    load_stage(0, 0);
    load_stage(1, 1);
    load_stage(2, 2);
    load_stage(3, 3);

    for (int kt = 0; kt < KT_PER; ++kt) {
        cp_wait<3>();
        __syncthreads();
        if (kt + 4 < KT_PER) load_stage((kt + 4) % NSTAGE, kt + 4);

        const uint32_t st  = sbase + (kt % NSTAGE) * STAGE_B;
        const uint32_t sah = st;
        const uint32_t sal = st + SUBT_B;
        const uint32_t sbh = st + 2 * SUBT_B;
        const uint32_t sbl = st + 3 * SUBT_B;

        #pragma unroll
        for (int ks = 0; ks < 2; ++ks) {
            uint32_t bh[2][4], bl[2][4];
            #pragma unroll
            for (int pr = 0; pr < 2; ++pr) {
                ldsm_x4(bh[pr], sbh + (b_row + pr * 16) * SROW + (ks * 2 + b_seg) * 16);
                ldsm_x4(bl[pr], sbl + (b_row + pr * 16) * SROW + (ks * 2 + b_seg) * 16);
            }

            uint32_t ah[4][4], al[4][4];
            #pragma unroll
            for (int mf = 0; mf < 4; ++mf) {
                ldsm_x4(ah[mf], sah + (a_row + mf * 16) * SROW + (ks * 2 + a_seg) * 16);
                ldsm_x4(al[mf], sal + (a_row + mf * 16) * SROW + (ks * 2 + a_seg) * 16);
            }

            #pragma unroll
            for (int mf = 0; mf < 4; ++mf)
                #pragma unroll
                for (int nf = 0; nf < 4; ++nf)
                    mma_f16(acc[mf][nf], ah[mf], bh[nf >> 1][(nf & 1) * 2], bh[nf >> 1][(nf & 1) * 2 + 1]);
            #pragma unroll
            for (int mf = 0; mf < 4; ++mf)
                #pragma unroll
                for (int nf = 0; nf < 4; ++nf)
                    mma_f16(acc[mf][nf], al[mf], bh[nf >> 1][(nf & 1) * 2], bh[nf >> 1][(nf & 1) * 2 + 1]);
            #pragma unroll
            for (int mf = 0; mf < 4; ++mf)
                #pragma unroll
                for (int nf = 0; nf < 4; ++nf)
                    mma_f16(acc[mf][nf], ah[mf], bl[nf >> 1][(nf & 1) * 2], bl[nf >> 1][(nf & 1) * 2 + 1]);
        }
    }

    // epilogue -> g_partial[z][m][n]
    const int group = lane >> 2;
    const int quad  = lane & 3;
    #pragma unroll
    for (int mf = 0; mf < 4; ++mf) {
        int row0 = mBase + warpM * 64 + mf * 16 + group;
        #pragma unroll
        for (int nf = 0; nf < 4; ++nf) {
            int col = nBase + warpN * 32 + nf * 8 + quad * 2;
            float* p0 = g_partial + ((size_t)z * NROI + row0) * NDF + col;
            float* p1 = p0 + (size_t)8 * NDF;
            *(float2*)p0 = make_float2(acc[mf][nf][0], acc[mf][nf][1]);
            *(float2*)p1 = make_float2(acc[mf][nf][2], acc[mf][nf][3]);
        }
    }
}

// ---------------- kernel 3: fused reduce + bias + cluster (4 rois/block) ----------------
__global__ void cluster_fused_kernel(const float* __restrict__ norms,
                                     const float* __restrict__ b_vis,
                                     const float* __restrict__ w_spc,
                                     const float* __restrict__ b_spc,
                                     const float* __restrict__ cent,
                                     float* __restrict__ Z,
                                     float* __restrict__ out_s,
                                     float* __restrict__ out_c) {
    __shared__ __align__(16) float zrow[4][NDF];
    __shared__ float sdist[4][NCLUS];
    __shared__ float ssum[4];
    __shared__ int   sarg[4];

    const int m0  = blockIdx.x * 4;
    const int tid = threadIdx.x;
    float nm[4];
    #pragma unroll
    for (int j = 0; j < 4; ++j) nm[j] = norms[m0 + j];

    for (int d = tid; d < NDF; d += 256) {
        float base = b_vis[d] + b_spc[d];
        float w = w_spc[d];
        float a[4];
        #pragma unroll
        for (int j = 0; j < 4; ++j) a[j] = base + nm[j] * w;
        for (int zz = 0; zz < SPLITK; ++zz) {
            const float* pp = g_partial + ((size_t)zz * NROI + m0) * NDF + d;
            #pragma unroll
            for (int j = 0; j < 4; ++j) a[j] += pp[(size_t)j * NDF];
        }
        #pragma unroll
        for (int j = 0; j < 4; ++j) {
            zrow[j][d] = a[j];
            Z[(size_t)(m0 + j) * NDF + d] = a[j];
        }
    }
    __syncthreads();

    const int warp = tid >> 5;
    const int lane = tid & 31;
    for (int k = warp; k < NCLUS; k += 8) {
        const float4* ck = (const float4*)(cent + (size_t)k * NDF);
        float s[4] = {0.f, 0.f, 0.f, 0.f};
        #pragma unroll
        for (int i = 0; i < 8; ++i) {
            int d4 = i * 32 + lane;
            float4 c = ck[d4];
            #pragma unroll
            for (int j = 0; j < 4; ++j) {
                float4 zv = *(const float4*)&zrow[j][d4 * 4];
                float t;
                t = zv.x - c.x; s[j] += t * t;
                t = zv.y - c.y; s[j] += t * t;
                t = zv.z - c.z; s[j] += t * t;
                t = zv.w - c.w; s[j] += t * t;
            }
        }
        #pragma unroll
        for (int o = 16; o; o >>= 1)
            #pragma unroll
            for (int j = 0; j < 4; ++j)
                s[j] += __shfl_xor_sync(0xffffffffu, s[j], o);
        if (lane == 0)
            #pragma unroll
            for (int j = 0; j < 4; ++j) sdist[j][k] = sqrtf(s[j]);
    }
    __syncthreads();

    if (tid < 4) {
        float sum = 0.0f, best = -1.0f;
        int bi = 0;
        for (int k = 0; k < NCLUS; ++k) {
            float st = 1.0f / (1.0f + sdist[tid][k]);
            sum += st;
            if (st > best) { best = st; bi = k; }
        }
        ssum[tid] = sum;
        sarg[tid] = bi;
    }
    __syncthreads();

    {
        const int j = tid >> 6;          // 0..3
        const int kk = tid & 63;         // 0..63
        if (kk < NCLUS)
            out_s[(size_t)(m0 + j) * NCLUS + kk] = (1.0f / (1.0f + sdist[j][kk])) / ssum[j];
    }
    if (tid < 4) out_c[m0 + tid] = (float)sarg[tid];
}

// ---------------- launch ----------------
extern "C" void kernel_launch(void* const* d_in, const int* in_sizes, int n_in,
                              void* d_out, int out_size) {
    const float* z_vis     = (const float*)d_in[0];
    const float* bboxs     = (const float*)d_in[1];
    const float* norms     = (const float*)d_in[2];
    const float* w_vis     = (const float*)d_in[3];
    const float* b_vis     = (const float*)d_in[4];
    const float* w_spc     = (const float*)d_in[5];
    const float* b_spc     = (const float*)d_in[6];
    const float* centroids = (const float*)d_in[7];

    float* out = (float*)d_out;
    float* Z = out;
    float* S = out + (size_t)NROI * NDF;
    float* C = S + (size_t)NROI * NCLUS;

    cudaFuncSetAttribute(gemm_hmma, cudaFuncAttributeMaxDynamicSharedMemorySize, SMEM_DYN);

    producers_kernel<<<NROI * ROIQ + NDF, 256>>>(z_vis, bboxs, w_vis);

    dim3 gg(NDF / BN, NROI / BM, SPLITK);        // (8, 4, 23) = 736 CTAs
    gemm_hmma<<<gg, 256, SMEM_DYN>>>(0);

    cluster_fused_kernel<<<NROI / 4, 256>>>(norms, b_vis, w_spc, b_spc, centroids, Z, S, C);
}

// round 12
// speedup vs baseline: 1.5673x; 1.1221x over previous
#include <cuda_runtime.h>
#include <cuda_fp16.h>
#include <math.h>
#include <stdint.h>

// ---------------- problem constants ----------------
#define SN_     32
#define NROI    512
#define NCH     480
#define TFRM    4
#define FY      45
#define FX      80
#define OSZ     7
#define DIN     23520
#define NDF     1024
#define NCLUS   50
#define KTOT    23520
#define KPAD    23552          // 736 k-tiles of 32
#define SPLITK  23
#define KT_PER  32             // 736 / 23

// roi split
#define ROIQ    4
#define ROICH   (DIN / ROIQ)   // 5880

// GEMM tiling
#define BM 128
#define BN 128
#define BK 32                  // fp16 elems per k-tile (64B rows)
#define SROW 80                // 64B data + 16B pad (conflict-free ldsm)
#define SUBT_B (BM * SROW)     // 10240 per sub-tile
#define STAGE_B (4 * SUBT_B)   // Ah + Al + Bh + Bl = 40960
#define NSTAGE 2
#define SMEM_DYN (NSTAGE * STAGE_B)   // 81920 -> 2 CTAs/SM

// ---------------- scratch ----------------
__device__ __align__(128) __half g_pl_hi[(size_t)NROI * KPAD];   // 24 MB
__device__ __align__(128) __half g_pl_lo[(size_t)NROI * KPAD];   // 24 MB
__device__ __align__(128) __half g_w_hi [(size_t)NDF  * KPAD];   // 48 MB
__device__ __align__(128) __half g_w_lo [(size_t)NDF  * KPAD];   // 48 MB
__device__ float g_partial[(size_t)SPLITK * NROI * NDF];         // 48 MB

// ---------------- helpers ----------------
__device__ __forceinline__ uint32_t smem_u32(const void* p) {
    uint32_t a;
    asm("{ .reg .u64 t; cvta.to.shared.u64 t, %1; cvt.u32.u64 %0, t; }" : "=r"(a) : "l"(p));
    return a;
}
__device__ __forceinline__ void cp_async16(uint32_t dst, const void* src) {
    asm volatile("cp.async.cg.shared.global [%0], [%1], 16;" :: "r"(dst), "l"(src) : "memory");
}
__device__ __forceinline__ void cp_commit() {
    asm volatile("cp.async.commit_group;" ::: "memory");
}
template <int N>
__device__ __forceinline__ void cp_wait() {
    asm volatile("cp.async.wait_group %0;" :: "n"(N) : "memory");
}
__device__ __forceinline__ void ldsm_x4(uint32_t* r, uint32_t addr) {
    asm volatile("ldmatrix.sync.aligned.m8n8.x4.shared.b16 {%0,%1,%2,%3}, [%4];"
                 : "=r"(r[0]), "=r"(r[1]), "=r"(r[2]), "=r"(r[3]) : "r"(addr));
}
__device__ __forceinline__ void mma_f16(float* c, const uint32_t* a, uint32_t b0, uint32_t b1) {
    asm volatile(
        "mma.sync.aligned.m16n8k16.row.col.f32.f16.f16.f32 "
        "{%0,%1,%2,%3}, {%4,%5,%6,%7}, {%8,%9}, {%0,%1,%2,%3};"
        : "+f"(c[0]), "+f"(c[1]), "+f"(c[2]), "+f"(c[3])
        : "r"(a[0]), "r"(a[1]), "r"(a[2]), "r"(a[3]), "r"(b0), "r"(b1));
}
__device__ __forceinline__ float nan_to_num(float v) {
    if (isnan(v)) return 0.0f;
    if (isinf(v)) return v > 0.0f ? 3.4028234663852886e38f : -3.4028234663852886e38f;
    return v;
}
// split two floats -> packed fp16 hi pair + lo pair
__device__ __forceinline__ void split2(float x, float y, uint32_t& hi, uint32_t& lo) {
    __half2 h = __floats2half2_rn(x, y);
    float2 hf = __half22float2(h);
    __half2 l = __floats2half2_rn(x - hf.x, y - hf.y);
    hi = *(uint32_t*)&h;
    lo = *(uint32_t*)&l;
}

// ---------------- kernel 1: fused producers ----------------
// blocks [0, NROI*ROIQ): quarter-RoI-align -> pooled hi/lo fp16
// blocks [NROI*ROIQ, NROI*ROIQ+NDF): w_vis row -> w hi/lo fp16
__global__ void producers_kernel(const float* __restrict__ zvis,
                                 const float* __restrict__ bboxs,
                                 const float* __restrict__ Wv) {
    const int bid = blockIdx.x;
    const int tid = threadIdx.x;

    if (bid >= NROI * ROIQ) {
        // ---- w_vis conversion: 8 floats -> uint4 hi + uint4 lo per iter ----
        const int row = bid - NROI * ROIQ;
        const float4* s4 = (const float4*)(Wv + (size_t)row * KTOT);
        uint4* dh = (uint4*)(g_w_hi + (size_t)row * KPAD);
        uint4* dl = (uint4*)(g_w_lo + (size_t)row * KPAD);
        for (int c8 = tid; c8 < KPAD / 8; c8 += 256) {
            uint4 hi, lo;
            if (c8 < KTOT / 8) {
                float4 v0 = s4[c8 * 2];
                float4 v1 = s4[c8 * 2 + 1];
                split2(v0.x, v0.y, hi.x, lo.x);
                split2(v0.z, v0.w, hi.y, lo.y);
                split2(v1.x, v1.y, hi.z, lo.z);
                split2(v1.z, v1.w, hi.w, lo.w);
            } else {
                hi = make_uint4(0, 0, 0, 0);
                lo = make_uint4(0, 0, 0, 0);
            }
            dh[c8] = hi;
            dl[c8] = lo;
        }
        return;
    }

    // ---- quarter-RoI-align path ----
    __shared__ int   s_off[49][4];
    __shared__ float s_w[49][4];

    const int r = bid >> 2;           // roi index
    const int q = bid & 3;            // quarter index
    const int b = r / SN_;

    if (tid < 49) {
        const float* bb = bboxs + (size_t)r * 4;
        const float sc = 0.0625f;
        float x1 = nan_to_num(bb[0] * sc) - 0.5f;
        float y1 = nan_to_num(bb[1] * sc) - 0.5f;
        float x2 = nan_to_num(bb[2] * sc) - 0.5f;
        float y2 = nan_to_num(bb[3] * sc) - 0.5f;
        float bw = (x2 - x1) * (1.0f / OSZ);
        float bh = (y2 - y1) * (1.0f / OSZ);

        int py = tid / OSZ, px = tid - py * OSZ;
        float y = y1 + ((float)py + 0.5f) * bh;
        float x = x1 + ((float)px + 0.5f) * bw;
        bool valid = (y > -1.0f) && (y < (float)FY) && (x > -1.0f) && (x < (float)FX);
        float yc = fminf(fmaxf(y, 0.0f), (float)(FY - 1));
        float xc = fminf(fmaxf(x, 0.0f), (float)(FX - 1));
        int yl = (int)floorf(yc);
        int xl = (int)floorf(xc);
        int yh = min(yl + 1, FY - 1);
        int xh = min(xl + 1, FX - 1);
        float ly = yc - (float)yl, lx = xc - (float)xl;
        float hy = 1.0f - ly, hx = 1.0f - lx;
        float vm = valid ? 1.0f : 0.0f;

        s_off[tid][0] = yl * FX + xl;
        s_off[tid][1] = yl * FX + xh;
        s_off[tid][2] = yh * FX + xl;
        s_off[tid][3] = yh * FX + xh;
        s_w[tid][0] = hy * hx * vm;
        s_w[tid][1] = hy * lx * vm;
        s_w[tid][2] = ly * hx * vm;
        s_w[tid][3] = ly * lx * vm;
    }
    __syncthreads();

    const float* fbase = zvis + (size_t)b * NCH * TFRM * FY * FX + (size_t)3 * FY * FX;
    __half* ohi = g_pl_hi + (size_t)r * KPAD;
    __half* olo = g_pl_lo + (size_t)r * KPAD;

    const int kend = (q + 1) * ROICH;
    for (int k = q * ROICH + tid; k < kend; k += 256) {
        int c = k / 49;
        int p = k - c * 49;
        const float* f = fbase + (size_t)c * (TFRM * FY * FX);
        float v = s_w[p][0] * f[s_off[p][0]]
                + s_w[p][1] * f[s_off[p][1]]
                + s_w[p][2] * f[s_off[p][2]]
                + s_w[p][3] * f[s_off[p][3]];
        __half h = __float2half_rn(v);
        ohi[k] = h;
        olo[k] = __float2half_rn(v - __half2float(h));
    }
    if (q == 3 && tid < (KPAD - DIN)) {
        ohi[DIN + tid] = __float2half_rn(0.0f);
        olo[DIN + tid] = __float2half_rn(0.0f);
    }
}

// ---------------- kernel 2: fp16 three-term HMMA GEMM (split-K 23, 2-stage, 2 CTA/SM) ----------------
// acc = Ah*Bh + Al*Bh + Ah*Bl   (drops only Al*Bl ~ 2^-24)
__global__ void __launch_bounds__(256, 2) gemm_hmma(int) {
    extern __shared__ __align__(16) char smem[];

    const int tid   = threadIdx.x;
    const int warp  = tid >> 5;
    const int lane  = tid & 31;
    const int nBase = blockIdx.x * BN;
    const int mBase = blockIdx.y * BM;
    const int z     = blockIdx.z;

    const uint32_t sbase = smem_u32(smem);

    // loader mapping
    const int lrow = tid >> 2;        // 0..63
    const int lseg = tid & 3;         // 16B segment

    // compute mapping
    const int warpM = warp >> 2;      // 0..1 -> *64
    const int warpN = warp & 3;       // 0..3 -> *32
    const uint32_t a_row = (uint32_t)(warpM * 64 + (lane & 15));
    const uint32_t a_seg = (uint32_t)(lane >> 4);
    const uint32_t b_row = (uint32_t)(warpN * 32 + ((lane >> 4) << 3) + (lane & 7));
    const uint32_t b_seg = (uint32_t)((lane >> 3) & 1);

    float acc[4][4][4];
    #pragma unroll
    for (int i = 0; i < 4; ++i)
        #pragma unroll
        for (int j = 0; j < 4; ++j)
            #pragma unroll
            for (int q = 0; q < 4; ++q) acc[i][j][q] = 0.0f;

    auto load_stage = [&](int s, int kt) {
        const int koff = (z * KT_PER + kt) * BK;
        const uint32_t st = sbase + s * STAGE_B;
        const __half* ah0 = g_pl_hi + (size_t)(mBase + lrow)      * KPAD + koff + lseg * 8;
        const __half* ah1 = g_pl_hi + (size_t)(mBase + lrow + 64) * KPAD + koff + lseg * 8;
        const __half* al0 = g_pl_lo + (size_t)(mBase + lrow)      * KPAD + koff + lseg * 8;
        const __half* al1 = g_pl_lo + (size_t)(mBase + lrow + 64) * KPAD + koff + lseg * 8;
        const __half* bh0 = g_w_hi + (size_t)(nBase + lrow)      * KPAD + koff + lseg * 8;
        const __half* bh1 = g_w_hi + (size_t)(nBase + lrow + 64) * KPAD + koff + lseg * 8;
        const __half* bl0 = g_w_lo + (size_t)(nBase + lrow)      * KPAD + koff + lseg * 8;
        const __half* bl1 = g_w_lo + (size_t)(nBase + lrow + 64) * KPAD + koff + lseg * 8;
        cp_async16(st +              lrow * SROW        + lseg * 16, ah0);
        cp_async16(st +             (lrow + 64) * SROW  + lseg * 16, ah1);
        cp_async16(st + SUBT_B     + lrow * SROW        + lseg * 16, al0);
        cp_async16(st + SUBT_B     + (lrow + 64) * SROW + lseg * 16, al1);
        cp_async16(st + 2 * SUBT_B + lrow * SROW        + lseg * 16, bh0);
        cp_async16(st + 2 * SUBT_B + (lrow + 64) * SROW + lseg * 16, bh1);
        cp_async16(st + 3 * SUBT_B + lrow * SROW        + lseg * 16, bl0);
        cp_async16(st + 3 * SUBT_B + (lrow + 64) * SROW + lseg * 16, bl1);
        cp_commit();
    };

    // prologue: stage 0 <- kt 0
    load_stage(0, 0);

    for (int kt = 0; kt < KT_PER; ++kt) {
        cp_wait<0>();          // stage kt resident
        __syncthreads();       // all warps done reading buffer (kt+1)&1 (last used in kt-1)
        if (kt + 1 < KT_PER) load_stage((kt + 1) & 1, kt + 1);

        const uint32_t st  = sbase + (kt & 1) * STAGE_B;
        const uint32_t sah = st;
        const uint32_t sal = st + SUBT_B;
        const uint32_t sbh = st + 2 * SUBT_B;
        const uint32_t sbl = st + 3 * SUBT_B;

        #pragma unroll
        for (int ks = 0; ks < 2; ++ks) {
            uint32_t bh[2][4], bl[2][4];
            #pragma unroll
            for (int pr = 0; pr < 2; ++pr) {
                ldsm_x4(bh[pr], sbh + (b_row + pr * 16) * SROW + (ks * 2 + b_seg) * 16);
                ldsm_x4(bl[pr], sbl + (b_row + pr * 16) * SROW + (ks * 2 + b_seg) * 16);
            }

            uint32_t ah[4][4], al[4][4];
            #pragma unroll
            for (int mf = 0; mf < 4; ++mf) {
                ldsm_x4(ah[mf], sah + (a_row + mf * 16) * SROW + (ks * 2 + a_seg) * 16);
                ldsm_x4(al[mf], sal + (a_row + mf * 16) * SROW + (ks * 2 + a_seg) * 16);
            }

            #pragma unroll
            for (int mf = 0; mf < 4; ++mf)
                #pragma unroll
                for (int nf = 0; nf < 4; ++nf)
                    mma_f16(acc[mf][nf], ah[mf], bh[nf >> 1][(nf & 1) * 2], bh[nf >> 1][(nf & 1) * 2 + 1]);
            #pragma unroll
            for (int mf = 0; mf < 4; ++mf)
                #pragma unroll
                for (int nf = 0; nf < 4; ++nf)
                    mma_f16(acc[mf][nf], al[mf], bh[nf >> 1][(nf & 1) * 2], bh[nf >> 1][(nf & 1) * 2 + 1]);
            #pragma unroll
            for (int mf = 0; mf < 4; ++mf)
                #pragma unroll
                for (int nf = 0; nf < 4; ++nf)
                    mma_f16(acc[mf][nf], ah[mf], bl[nf >> 1][(nf & 1) * 2], bl[nf >> 1][(nf & 1) * 2 + 1]);
        }
    }

    // epilogue -> g_partial[z][m][n]
    const int group = lane >> 2;
    const int quad  = lane & 3;
    #pragma unroll
    for (int mf = 0; mf < 4; ++mf) {
        int row0 = mBase + warpM * 64 + mf * 16 + group;
        #pragma unroll
        for (int nf = 0; nf < 4; ++nf) {
            int col = nBase + warpN * 32 + nf * 8 + quad * 2;
            float* p0 = g_partial + ((size_t)z * NROI + row0) * NDF + col;
            float* p1 = p0 + (size_t)8 * NDF;
            *(float2*)p0 = make_float2(acc[mf][nf][0], acc[mf][nf][1]);
            *(float2*)p1 = make_float2(acc[mf][nf][2], acc[mf][nf][3]);
        }
    }
}

// ---------------- kernel 3: fused reduce + bias + cluster (4 rois/block) ----------------
__global__ void cluster_fused_kernel(const float* __restrict__ norms,
                                     const float* __restrict__ b_vis,
                                     const float* __restrict__ w_spc,
                                     const float* __restrict__ b_spc,
                                     const float* __restrict__ cent,
                                     float* __restrict__ Z,
                                     float* __restrict__ out_s,
                                     float* __restrict__ out_c) {
    __shared__ __align__(16) float zrow[4][NDF];
    __shared__ float sdist[4][NCLUS];
    __shared__ float ssum[4];
    __shared__ int   sarg[4];

    const int m0  = blockIdx.x * 4;
    const int tid = threadIdx.x;
    float nm[4];
    #pragma unroll
    for (int j = 0; j < 4; ++j) nm[j] = norms[m0 + j];

    for (int d = tid; d < NDF; d += 256) {
        float base = b_vis[d] + b_spc[d];
        float w = w_spc[d];
        float a[4];
        #pragma unroll
        for (int j = 0; j < 4; ++j) a[j] = base + nm[j] * w;
        for (int zz = 0; zz < SPLITK; ++zz) {
            const float* pp = g_partial + ((size_t)zz * NROI + m0) * NDF + d;
            #pragma unroll
            for (int j = 0; j < 4; ++j) a[j] += pp[(size_t)j * NDF];
        }
        #pragma unroll
        for (int j = 0; j < 4; ++j) {
            zrow[j][d] = a[j];
            Z[(size_t)(m0 + j) * NDF + d] = a[j];
        }
    }
    __syncthreads();

    const int warp = tid >> 5;
    const int lane = tid & 31;
    for (int k = warp; k < NCLUS; k += 8) {
        const float4* ck = (const float4*)(cent + (size_t)k * NDF);
        float s[4] = {0.f, 0.f, 0.f, 0.f};
        #pragma unroll
        for (int i = 0; i < 8; ++i) {
            int d4 = i * 32 + lane;
            float4 c = ck[d4];
            #pragma unroll
            for (int j = 0; j < 4; ++j) {
                float4 zv = *(const float4*)&zrow[j][d4 * 4];
                float t;
                t = zv.x - c.x; s[j] += t * t;
                t = zv.y - c.y; s[j] += t * t;
                t = zv.z - c.z; s[j] += t * t;
                t = zv.w - c.w; s[j] += t * t;
            }
        }
        #pragma unroll
        for (int o = 16; o; o >>= 1)
            #pragma unroll
            for (int j = 0; j < 4; ++j)
                s[j] += __shfl_xor_sync(0xffffffffu, s[j], o);
        if (lane == 0)
            #pragma unroll
            for (int j = 0; j < 4; ++j) sdist[j][k] = sqrtf(s[j]);
    }
    __syncthreads();

    if (tid < 4) {
        float sum = 0.0f, best = -1.0f;
        int bi = 0;
        for (int k = 0; k < NCLUS; ++k) {
            float st = 1.0f / (1.0f + sdist[tid][k]);
            sum += st;
            if (st > best) { best = st; bi = k; }
        }
        ssum[tid] = sum;
        sarg[tid] = bi;
    }
    __syncthreads();

    {
        const int j = tid >> 6;          // 0..3
        const int kk = tid & 63;         // 0..63
        if (kk < NCLUS)
            out_s[(size_t)(m0 + j) * NCLUS + kk] = (1.0f / (1.0f + sdist[j][kk])) / ssum[j];
    }
    if (tid < 4) out_c[m0 + tid] = (float)sarg[tid];
}

// ---------------- launch ----------------
extern "C" void kernel_launch(void* const* d_in, const int* in_sizes, int n_in,
                              void* d_out, int out_size) {
    const float* z_vis     = (const float*)d_in[0];
    const float* bboxs     = (const float*)d_in[1];
    const float* norms     = (const float*)d_in[2];
    const float* w_vis     = (const float*)d_in[3];
    const float* b_vis     = (const float*)d_in[4];
    const float* w_spc     = (const float*)d_in[5];
    const float* b_spc     = (const float*)d_in[6];
    const float* centroids = (const float*)d_in[7];

    float* out = (float*)d_out;
    float* Z = out;
    float* S = out + (size_t)NROI * NDF;
    float* C = S + (size_t)NROI * NCLUS;

    cudaFuncSetAttribute(gemm_hmma, cudaFuncAttributeMaxDynamicSharedMemorySize, SMEM_DYN);

    producers_kernel<<<NROI * ROIQ + NDF, 256>>>(z_vis, bboxs, w_vis);

    dim3 gg(NDF / BN, NROI / BM, SPLITK);        // (8, 4, 23) = 736 CTAs, 2/SM
    gemm_hmma<<<gg, 256, SMEM_DYN>>>(0);

    cluster_fused_kernel<<<NROI / 4, 256>>>(norms, b_vis, w_spc, b_spc, centroids, Z, S, C);
}